// round 16
// baseline (speedup 1.0000x reference)
#include <cuda_runtime.h>
#include <cuda_bf16.h>
#include <cstdint>

// Problem shape: A [64, 2048, 64], B [64, 64, 2048], out [64, 2048, 2048] (batch=4*16 flattened)
#define NBATCH 64
#define SDIM   2048
#define TDIM   2048
#define DDIM   64
#define NA_EL  (NBATCH * SDIM * DDIM)   // 8388608
#define NB_EL  (NBATCH * DDIM * TDIM)   // 8388608
#define MM_BLOCKS 1024                  // minmax blocks per tensor
#define NGROUPS 2048                    // super-groups: (b, m-tile, n-half), 8 tiles each
#define GEMM_GRID 296                   // 2 CTAs per SM (148 SMs) -> all co-resident

// ---- device-global state (scratch; no allocations allowed) ----
__device__ float g_pmin[2][MM_BLOCKS], g_pmax[2][MM_BLOCKS];
__device__ int   g_arrive, g_done;      // grid barrier counters (self-resetting)
__device__ __nv_bfloat16 g_Aq[NA_EL];
__device__ __nv_bfloat16 g_Bq[NB_EL];

// ---- pass 1: per-tensor min/max partials (deterministic, no atomics, no reset) ----
// Exactly 8 grid-stride steps per thread -> fully unrolled for 8-deep LDG MLP.
__global__ void __launch_bounds__(256) k_minmax(const float* __restrict__ A,
                                               const float* __restrict__ B) {
    const int sel = blockIdx.z;
    const float4* x4 = (const float4*)(sel ? B : A);
    const int base = blockIdx.x * blockDim.x + threadIdx.x;
    const int stride = MM_BLOCKS * 256;           // n4 / stride == 8 exactly
    float4 v[8];
    #pragma unroll
    for (int j = 0; j < 8; j++) v[j] = x4[base + j * stride];
    float vmin = 0.0f, vmax = 0.0f;
    #pragma unroll
    for (int j = 0; j < 8; j++) {
        vmin = fminf(vmin, fminf(fminf(v[j].x, v[j].y), fminf(v[j].z, v[j].w)));
        vmax = fmaxf(vmax, fmaxf(fmaxf(v[j].x, v[j].y), fmaxf(v[j].z, v[j].w)));
    }
    #pragma unroll
    for (int o = 16; o > 0; o >>= 1) {
        vmin = fminf(vmin, __shfl_xor_sync(0xffffffffu, vmin, o));
        vmax = fmaxf(vmax, __shfl_xor_sync(0xffffffffu, vmax, o));
    }
    __shared__ float smin[8], smax[8];
    int wid = threadIdx.x >> 5, lane = threadIdx.x & 31;
    if (lane == 0) { smin[wid] = vmin; smax[wid] = vmax; }
    __syncthreads();
    if (threadIdx.x == 0) {
        float m = smin[0], M = smax[0];
        #pragma unroll
        for (int w = 1; w < 8; w++) { m = fminf(m, smin[w]); M = fmaxf(M, smax[w]); }
        g_pmin[sel][blockIdx.x] = m;
        g_pmax[sel][blockIdx.x] = M;
    }
}

// ---- pass 2: fused quant + GEMM ----
// Phase 0: every CTA reduces the minmax partials -> quant params (deterministic,
// identical in all CTAs), quantizes its grid-stride slice of A and B to
// INTEGER-valued bf16 (exact: |q-zp| <= 255 < 2^8), then crosses a grid spin
// barrier (co-residency guaranteed: 296 CTAs at 2/SM).
// Phase 1: R13 GEMM core verbatim — persistent, CTA tile 128x128, A-reuse
// super-groups (8 n-tiles share one A tile), 3-stage cp.async B pipeline,
// single barrier per tile.
#define SA_ROWS 128
#define SA_COLS 72     // 64 + 8 pad (16B row shift -> no LDSM conflicts)
#define SB_ROWS 64
#define SB_COLS 136    // 128 + 8 pad
#define SA_BYTES (SA_ROWS * SA_COLS * 2)       // 18432
#define SB_BYTES (SB_ROWS * SB_COLS * 2)       // 17408
#define NSTAGE 3
#define SMEM_DYN (2 * SA_BYTES + NSTAGE * SB_BYTES)   // 89088 B (2 CTAs/SM)

__device__ __forceinline__ void cpa16(void* dst, const void* src) {
    uint32_t d = (uint32_t)__cvta_generic_to_shared(dst);
    asm volatile("cp.async.cg.shared.global [%0], [%1], 16;" :: "r"(d), "l"(src));
}

__global__ void __launch_bounds__(256, 2) k_gemm(float* __restrict__ out,
                                                 const float* __restrict__ A,
                                                 const float* __restrict__ B) {
    extern __shared__ char smem_raw[];

    const int tid = threadIdx.x;
    const int bid = blockIdx.x;
    const int warp = tid >> 5, lane = tid & 31;

    // ================= phase 0: params + quantize A and B =================
    __shared__ float sred[4][8];
    __shared__ float s_dA, s_zA, s_dB, s_zB;
    {
        float mA =  1e30f, MA = -1e30f, mB =  1e30f, MB = -1e30f;
        #pragma unroll
        for (int j = 0; j < MM_BLOCKS / 256; j++) {
            int idx = tid + j * 256;
            mA = fminf(mA, g_pmin[0][idx]); MA = fmaxf(MA, g_pmax[0][idx]);
            mB = fminf(mB, g_pmin[1][idx]); MB = fmaxf(MB, g_pmax[1][idx]);
        }
        #pragma unroll
        for (int o = 16; o > 0; o >>= 1) {
            mA = fminf(mA, __shfl_xor_sync(0xffffffffu, mA, o));
            MA = fmaxf(MA, __shfl_xor_sync(0xffffffffu, MA, o));
            mB = fminf(mB, __shfl_xor_sync(0xffffffffu, mB, o));
            MB = fmaxf(MB, __shfl_xor_sync(0xffffffffu, MB, o));
        }
        if (lane == 0) { sred[0][warp] = mA; sred[1][warp] = MA; sred[2][warp] = mB; sred[3][warp] = MB; }
        __syncthreads();
        if (tid == 0) {
            float minA = sred[0][0], maxA = sred[1][0], minB = sred[2][0], maxB = sred[3][0];
            #pragma unroll
            for (int w = 1; w < 8; w++) {
                minA = fminf(minA, sred[0][w]); maxA = fmaxf(maxA, sred[1][w]);
                minB = fminf(minB, sred[2][w]); maxB = fmaxf(maxB, sred[3][w]);
            }
            float dA = fmaxf(__fdiv_rn(maxA - minA, 255.0f), 1e-8f);
            float dB = fmaxf(__fdiv_rn(maxB - minB, 255.0f), 1e-8f);
            s_dA = dA; s_zA = rintf(__fdiv_rn(-minA, dA));
            s_dB = dB; s_zB = rintf(__fdiv_rn(-minB, dB));
        }
        __syncthreads();
        const float dA = s_dA, zA = s_zA, dB = s_dB, zB = s_zB;

        const float4* A4 = (const float4*)A;
        const float4* B4 = (const float4*)B;
        uint2* oa = (uint2*)g_Aq;
        uint2* ob = (uint2*)g_Bq;
        const int n4 = NA_EL / 4;
        const int STRIDE = GEMM_GRID * 256;
        for (int i = bid * 256 + tid; i < n4; i += STRIDE) {
            float4 a = A4[i];
            float4 b = B4[i];
            float qa0 = fminf(fmaxf(rintf(__fdiv_rn(a.x, dA)) + zA, 0.0f), 255.0f) - zA;
            float qa1 = fminf(fmaxf(rintf(__fdiv_rn(a.y, dA)) + zA, 0.0f), 255.0f) - zA;
            float qa2 = fminf(fmaxf(rintf(__fdiv_rn(a.z, dA)) + zA, 0.0f), 255.0f) - zA;
            float qa3 = fminf(fmaxf(rintf(__fdiv_rn(a.w, dA)) + zA, 0.0f), 255.0f) - zA;
            float qb0 = fminf(fmaxf(rintf(__fdiv_rn(b.x, dB)) + zB, 0.0f), 255.0f) - zB;
            float qb1 = fminf(fmaxf(rintf(__fdiv_rn(b.y, dB)) + zB, 0.0f), 255.0f) - zB;
            float qb2 = fminf(fmaxf(rintf(__fdiv_rn(b.z, dB)) + zB, 0.0f), 255.0f) - zB;
            float qb3 = fminf(fmaxf(rintf(__fdiv_rn(b.w, dB)) + zB, 0.0f), 255.0f) - zB;
            __nv_bfloat162 pa0 = __floats2bfloat162_rn(qa0, qa1);
            __nv_bfloat162 pa1 = __floats2bfloat162_rn(qa2, qa3);
            __nv_bfloat162 pb0 = __floats2bfloat162_rn(qb0, qb1);
            __nv_bfloat162 pb1 = __floats2bfloat162_rn(qb2, qb3);
            uint2 ua, ub;
            ua.x = *(uint32_t*)&pa0; ua.y = *(uint32_t*)&pa1;
            ub.x = *(uint32_t*)&pb0; ub.y = *(uint32_t*)&pb1;
            oa[i] = ua;
            ob[i] = ub;
        }
    }

    // ---- grid barrier: all quant writes visible before any CTA's GEMM reads ----
    __syncthreads();
    if (tid == 0) {
        __threadfence();                       // release quant stores
        atomicAdd(&g_arrive, 1);
        while (atomicAdd(&g_arrive, 0) < GEMM_GRID) { }
        __threadfence();                       // acquire all CTAs' quant stores
    }
    __syncthreads();

    // ================= phase 1: GEMM (R13 core verbatim) =================
    const int wm = warp >> 2;      // 0..1 -> 64 rows each
    const int wn = warp & 3;       // 0..3 -> 32 cols each

    const int ar = tid >> 3, ac = (tid & 7) * 8;          // A rows ar+{0,32,64,96}
    const int br = tid >> 4, bc = (tid & 15) * 8;         // B rows br+{0,16,32,48}

    auto bufA = [&](int p) -> __nv_bfloat16 (*)[SA_COLS] {
        return (__nv_bfloat16 (*)[SA_COLS])(smem_raw + p * SA_BYTES);
    };
    auto stageB = [&](int st) -> __nv_bfloat16 (*)[SB_COLS] {
        return (__nv_bfloat16 (*)[SB_COLS])(smem_raw + 2 * SA_BYTES + st * SB_BYTES);
    };

    // local tile i -> group k = i>>3 (u = bid + k*GRID), j = i&7
    // u decode: b = u>>5, m-tile = (u>>1)&15, n-half = u&1
    const int ngroups = (NGROUPS - bid + GEMM_GRID - 1) / GEMM_GRID;
    const int L = ngroups * 8;

    auto load_group = [&](int i) {
        int k = i >> 3, j = i & 7;
        int u = bid + k * GEMM_GRID;
        int b  = u >> 5;
        int m0 = ((u >> 1) & 15) * 128;
        int n0 = (u & 1) * 1024 + j * 128;
        if ((i & 7) == 0) {
            const __nv_bfloat16* Ab = g_Aq + (size_t)b * SDIM * DDIM + (size_t)m0 * DDIM;
            __nv_bfloat16 (*sA)[SA_COLS] = bufA(k & 1);
            #pragma unroll
            for (int it = 0; it < 4; it++)
                cpa16(&sA[ar + it * 32][ac], Ab + (ar + it * 32) * DDIM + ac);
        }
        const __nv_bfloat16* Bb = g_Bq + (size_t)b * DDIM * TDIM + n0;
        __nv_bfloat16 (*sB)[SB_COLS] = stageB(i % 3);
        #pragma unroll
        for (int it = 0; it < 4; it++)
            cpa16(&sB[br + it * 16][bc], Bb + (size_t)(br + it * 16) * TDIM + bc);
        asm volatile("cp.async.commit_group;");
    };

    const float s = s_dA * s_dB;   // per-CTA deterministic scale

    load_group(0);
    if (L > 1) load_group(1);

    for (int i = 0; i < L; i++) {
        if (i + 1 < L) {
            asm volatile("cp.async.wait_group 1;");   // this tile's group done
        } else {
            asm volatile("cp.async.wait_group 0;");
        }
        __syncthreads();   // single barrier per iteration

        const int k = i >> 3, j = i & 7;
        const int u = bid + k * GEMM_GRID;
        const int b  = u >> 5;
        const int m0 = ((u >> 1) & 15) * 128;
        const int n0 = (u & 1) * 1024 + j * 128;

        __nv_bfloat16 (*sA)[SA_COLS] = bufA(k & 1);
        __nv_bfloat16 (*sB)[SB_COLS] = stageB(i % 3);

        float acc[4][4][4];
        #pragma unroll
        for (int mi = 0; mi < 4; mi++)
            #pragma unroll
            for (int ni = 0; ni < 4; ni++)
                #pragma unroll
                for (int q = 0; q < 4; q++) acc[mi][ni][q] = 0.0f;

        #pragma unroll
        for (int ks = 0; ks < 4; ks++) {
            const int k0 = ks * 16;
            uint32_t af[4][4];
            #pragma unroll
            for (int mi = 0; mi < 4; mi++) {
                int r = wm * 64 + mi * 16 + (lane & 15);
                int c = k0 + (lane >> 4) * 8;
                uint32_t addr = (uint32_t)__cvta_generic_to_shared(&sA[r][c]);
                asm volatile(
                    "ldmatrix.sync.aligned.m8n8.x4.shared.b16 {%0,%1,%2,%3}, [%4];"
                    : "=r"(af[mi][0]), "=r"(af[mi][1]), "=r"(af[mi][2]), "=r"(af[mi][3])
                    : "r"(addr));
            }
            uint32_t bf[4][2];
            #pragma unroll
            for (int nj = 0; nj < 2; nj++) {
                int r = k0 + (lane & 7) + ((lane >> 3) & 1) * 8;
                int c = wn * 32 + nj * 16 + (lane >> 4) * 8;
                uint32_t addr = (uint32_t)__cvta_generic_to_shared(&sB[r][c]);
                uint32_t t0, t1, t2, t3;
                asm volatile(
                    "ldmatrix.sync.aligned.m8n8.x4.trans.shared.b16 {%0,%1,%2,%3}, [%4];"
                    : "=r"(t0), "=r"(t1), "=r"(t2), "=r"(t3)
                    : "r"(addr));
                bf[nj * 2 + 0][0] = t0; bf[nj * 2 + 0][1] = t1;
                bf[nj * 2 + 1][0] = t2; bf[nj * 2 + 1][1] = t3;
            }
            #pragma unroll
            for (int mi = 0; mi < 4; mi++)
                #pragma unroll
                for (int ni = 0; ni < 4; ni++) {
                    asm volatile(
                        "mma.sync.aligned.m16n8k16.row.col.f32.bf16.bf16.f32 "
                        "{%0,%1,%2,%3}, {%4,%5,%6,%7}, {%8,%9}, {%0,%1,%2,%3};"
                        : "+f"(acc[mi][ni][0]), "+f"(acc[mi][ni][1]),
                          "+f"(acc[mi][ni][2]), "+f"(acc[mi][ni][3])
                        : "r"(af[mi][0]), "r"(af[mi][1]), "r"(af[mi][2]), "r"(af[mi][3]),
                          "r"(bf[ni][0]), "r"(bf[ni][1]));
                }
        }

        // epilogue stores (drain while loads for i+2 stream and next iter computes)
        {
            float* ob = out + (size_t)b * SDIM * TDIM;
            #pragma unroll
            for (int mi = 0; mi < 4; mi++) {
                #pragma unroll
                for (int ni = 0; ni < 4; ni++) {
                    int r = m0 + wm * 64 + mi * 16 + (lane >> 2);
                    int c = n0 + wn * 32 + ni * 8 + (lane & 3) * 2;
                    float2 v0 = make_float2(acc[mi][ni][0] * s, acc[mi][ni][1] * s);
                    float2 v1 = make_float2(acc[mi][ni][2] * s, acc[mi][ni][3] * s);
                    *(float2*)&ob[(size_t)r * TDIM + c]       = v0;
                    *(float2*)&ob[(size_t)(r + 8) * TDIM + c] = v1;
                }
            }
        }

        // prefetch local tile i+2 (B stage (i+2)%3 != current/next; A goes to
        // the idle parity buffer — races excluded by the top barrier)
        if (i + 2 < L) load_group(i + 2);
    }

    // ---- counter reset for next graph replay (deterministic) ----
    if (tid == 0) {
        int d = atomicAdd(&g_done, 1);
        if (d == GEMM_GRID - 1) {        // last CTA out resets both counters
            atomicExch(&g_arrive, 0);
            atomicExch(&g_done, 0);
        }
    }
}

extern "C" void kernel_launch(void* const* d_in, const int* in_sizes, int n_in,
                              void* d_out, int out_size) {
    const float* A = (const float*)d_in[0];
    const float* B = (const float*)d_in[1];
    float* out = (float*)d_out;

    cudaFuncSetAttribute(k_gemm, cudaFuncAttributeMaxDynamicSharedMemorySize, SMEM_DYN);

    k_minmax<<<dim3(MM_BLOCKS, 1, 2), 256>>>(A, B);
    k_gemm<<<GEMM_GRID, 256, SMEM_DYN>>>(out, A, B);
}

// round 17
// speedup vs baseline: 1.0510x; 1.0510x over previous
#include <cuda_runtime.h>
#include <cuda_bf16.h>
#include <cstdint>

// Problem shape: A [64, 2048, 64], B [64, 64, 2048], out [64, 2048, 2048] (batch=4*16 flattened)
#define NBATCH 64
#define SDIM   2048
#define TDIM   2048
#define DDIM   64
#define NA_EL  (NBATCH * SDIM * DDIM)   // 8388608
#define NB_EL  (NBATCH * DDIM * TDIM)   // 8388608
#define MM_BLOCKS 1024                  // minmax blocks per tensor
#define NGROUPS 2048                    // super-groups: (b, m-tile, n-half), 8 tiles each
#define GEMM_GRID 296                   // 2 CTAs per SM (148 SMs)

// ---- device-global state (scratch; no allocations allowed) ----
__device__ float g_pmin[2][MM_BLOCKS], g_pmax[2][MM_BLOCKS];
__device__ float g_scale;
__device__ __nv_bfloat16 g_Aq[NA_EL];
__device__ __nv_bfloat16 g_Bq[NB_EL];

// ---- pass 1: per-tensor min/max partials (deterministic, no atomics, no reset) ----
// Exactly 8 grid-stride steps per thread -> fully unrolled for 8-deep LDG MLP.
__global__ void __launch_bounds__(256) k_minmax(const float* __restrict__ A,
                                               const float* __restrict__ B) {
    const int sel = blockIdx.z;
    const float4* x4 = (const float4*)(sel ? B : A);
    const int base = blockIdx.x * blockDim.x + threadIdx.x;
    const int stride = MM_BLOCKS * 256;           // n4 / stride == 8 exactly
    float4 v[8];
    #pragma unroll
    for (int j = 0; j < 8; j++) v[j] = x4[base + j * stride];
    float vmin = 0.0f, vmax = 0.0f;
    #pragma unroll
    for (int j = 0; j < 8; j++) {
        vmin = fminf(vmin, fminf(fminf(v[j].x, v[j].y), fminf(v[j].z, v[j].w)));
        vmax = fmaxf(vmax, fmaxf(fmaxf(v[j].x, v[j].y), fmaxf(v[j].z, v[j].w)));
    }
    #pragma unroll
    for (int o = 16; o > 0; o >>= 1) {
        vmin = fminf(vmin, __shfl_xor_sync(0xffffffffu, vmin, o));
        vmax = fmaxf(vmax, __shfl_xor_sync(0xffffffffu, vmax, o));
    }
    __shared__ float smin[8], smax[8];
    int wid = threadIdx.x >> 5, lane = threadIdx.x & 31;
    if (lane == 0) { smin[wid] = vmin; smax[wid] = vmax; }
    __syncthreads();
    if (threadIdx.x == 0) {
        float m = smin[0], M = smax[0];
        #pragma unroll
        for (int w = 1; w < 8; w++) { m = fminf(m, smin[w]); M = fmaxf(M, smax[w]); }
        g_pmin[sel][blockIdx.x] = m;
        g_pmax[sel][blockIdx.x] = M;
    }
}

// ---- pass 2: quant params (recomputed per block; deterministic) + fake-quant ----
// 8 elements per thread (2x float4 load -> 1x uint4 store), exactly 2 unrolled
// grid-stride iterations. INTEGER-valued bf16 output (exact: |q-zp| <= 255).
__global__ void __launch_bounds__(256) k_quant(const float* __restrict__ A,
                                               const float* __restrict__ B) {
    const int t = threadIdx.x;
    float mA =  1e30f, MA = -1e30f, mB =  1e30f, MB = -1e30f;
    #pragma unroll
    for (int j = 0; j < MM_BLOCKS / 256; j++) {
        int idx = t + j * 256;
        mA = fminf(mA, g_pmin[0][idx]); MA = fmaxf(MA, g_pmax[0][idx]);
        mB = fminf(mB, g_pmin[1][idx]); MB = fmaxf(MB, g_pmax[1][idx]);
    }
    #pragma unroll
    for (int o = 16; o > 0; o >>= 1) {
        mA = fminf(mA, __shfl_xor_sync(0xffffffffu, mA, o));
        MA = fmaxf(MA, __shfl_xor_sync(0xffffffffu, MA, o));
        mB = fminf(mB, __shfl_xor_sync(0xffffffffu, mB, o));
        MB = fmaxf(MB, __shfl_xor_sync(0xffffffffu, MB, o));
    }
    __shared__ float sred[4][8];
    __shared__ float s_delta, s_zp;
    int wid = t >> 5, lane = t & 31;
    if (lane == 0) { sred[0][wid] = mA; sred[1][wid] = MA; sred[2][wid] = mB; sred[3][wid] = MB; }
    __syncthreads();
    if (t == 0) {
        float minA = sred[0][0], maxA = sred[1][0], minB = sred[2][0], maxB = sred[3][0];
        #pragma unroll
        for (int w = 1; w < 8; w++) {
            minA = fminf(minA, sred[0][w]); maxA = fmaxf(maxA, sred[1][w]);
            minB = fminf(minB, sred[2][w]); maxB = fmaxf(maxB, sred[3][w]);
        }
        float dA = fmaxf(__fdiv_rn(maxA - minA, 255.0f), 1e-8f);
        float dB = fmaxf(__fdiv_rn(maxB - minB, 255.0f), 1e-8f);
        if (blockIdx.z == 0) {
            s_delta = dA;
            s_zp = rintf(__fdiv_rn(-minA, dA));
        } else {
            s_delta = dB;
            s_zp = rintf(__fdiv_rn(-minB, dB));
        }
        if (blockIdx.x == 0 && blockIdx.z == 0) g_scale = dA * dB;
    }
    __syncthreads();
    const float delta = s_delta, zp = s_zp;

    const int sel = blockIdx.z;
    const float4* x4 = (const float4*)(sel ? B : A);
    uint4* o4 = (uint4*)(sel ? g_Bq : g_Aq);
    const int n8 = NA_EL / 8;                       // 1048576
    const int base = blockIdx.x * blockDim.x + t;   // grid 2048*256 -> 2 iters
    #pragma unroll
    for (int it = 0; it < 2; it++) {
        int i = base + it * (2048 * 256);
        if (i < n8) {
            float4 v0 = x4[2 * i];
            float4 v1 = x4[2 * i + 1];
            float q0 = fminf(fmaxf(rintf(__fdiv_rn(v0.x, delta)) + zp, 0.0f), 255.0f) - zp;
            float q1 = fminf(fmaxf(rintf(__fdiv_rn(v0.y, delta)) + zp, 0.0f), 255.0f) - zp;
            float q2 = fminf(fmaxf(rintf(__fdiv_rn(v0.z, delta)) + zp, 0.0f), 255.0f) - zp;
            float q3 = fminf(fmaxf(rintf(__fdiv_rn(v0.w, delta)) + zp, 0.0f), 255.0f) - zp;
            float q4 = fminf(fmaxf(rintf(__fdiv_rn(v1.x, delta)) + zp, 0.0f), 255.0f) - zp;
            float q5 = fminf(fmaxf(rintf(__fdiv_rn(v1.y, delta)) + zp, 0.0f), 255.0f) - zp;
            float q6 = fminf(fmaxf(rintf(__fdiv_rn(v1.z, delta)) + zp, 0.0f), 255.0f) - zp;
            float q7 = fminf(fmaxf(rintf(__fdiv_rn(v1.w, delta)) + zp, 0.0f), 255.0f) - zp;
            __nv_bfloat162 p0 = __floats2bfloat162_rn(q0, q1);
            __nv_bfloat162 p1 = __floats2bfloat162_rn(q2, q3);
            __nv_bfloat162 p2 = __floats2bfloat162_rn(q4, q5);
            __nv_bfloat162 p3 = __floats2bfloat162_rn(q6, q7);
            uint4 u;
            u.x = *(uint32_t*)&p0; u.y = *(uint32_t*)&p1;
            u.z = *(uint32_t*)&p2; u.w = *(uint32_t*)&p3;
            o4[i] = u;
        }
    }
}

// ---- pass 3: persistent GEMM, CTA tile 128x128, A-reuse grouping (R13 core) ----
// Super-group u = (b, m, n-half): 8 consecutive n-tiles share one A tile.
// A loaded ONCE per group (double-buffered by group parity); B keeps the
// 3-stage prefetch-depth-2 pipeline with a single barrier per tile.
// Output stores use evict-first (__stcs): write-once stream, protect B in L2.
#define SA_ROWS 128
#define SA_COLS 72     // 64 + 8 pad (16B row shift -> no LDSM conflicts)
#define SB_ROWS 64
#define SB_COLS 136    // 128 + 8 pad
#define SA_BYTES (SA_ROWS * SA_COLS * 2)       // 18432
#define SB_BYTES (SB_ROWS * SB_COLS * 2)       // 17408
#define NSTAGE 3
#define SMEM_DYN (2 * SA_BYTES + NSTAGE * SB_BYTES)   // 89088 B (2 CTAs/SM)

__device__ __forceinline__ void cpa16(void* dst, const void* src) {
    uint32_t d = (uint32_t)__cvta_generic_to_shared(dst);
    asm volatile("cp.async.cg.shared.global [%0], [%1], 16;" :: "r"(d), "l"(src));
}

__global__ void __launch_bounds__(256, 2) k_gemm(float* __restrict__ out) {
    extern __shared__ char smem_raw[];

    const int tid = threadIdx.x;
    const int bid = blockIdx.x;
    const int warp = tid >> 5, lane = tid & 31;
    const int wm = warp >> 2;      // 0..1 -> 64 rows each
    const int wn = warp & 3;       // 0..3 -> 32 cols each

    const int ar = tid >> 3, ac = (tid & 7) * 8;          // A rows ar+{0,32,64,96}
    const int br = tid >> 4, bc = (tid & 15) * 8;         // B rows br+{0,16,32,48}

    auto bufA = [&](int p) -> __nv_bfloat16 (*)[SA_COLS] {
        return (__nv_bfloat16 (*)[SA_COLS])(smem_raw + p * SA_BYTES);
    };
    auto stageB = [&](int st) -> __nv_bfloat16 (*)[SB_COLS] {
        return (__nv_bfloat16 (*)[SB_COLS])(smem_raw + 2 * SA_BYTES + st * SB_BYTES);
    };

    // local tile i -> group k = i>>3 (u = bid + k*GRID), j = i&7
    // u decode: b = u>>5, m-tile = (u>>1)&15, n-half = u&1
    const int ngroups = (NGROUPS - bid + GEMM_GRID - 1) / GEMM_GRID;
    const int L = ngroups * 8;

    // commit ONE cp.async group for local tile i: B(i) (+ A(u) when i%8==0)
    auto load_group = [&](int i) {
        int k = i >> 3, j = i & 7;
        int u = bid + k * GEMM_GRID;
        int b  = u >> 5;
        int m0 = ((u >> 1) & 15) * 128;
        int n0 = (u & 1) * 1024 + j * 128;
        if ((i & 7) == 0) {
            const __nv_bfloat16* Ab = g_Aq + (size_t)b * SDIM * DDIM + (size_t)m0 * DDIM;
            __nv_bfloat16 (*sA)[SA_COLS] = bufA(k & 1);
            #pragma unroll
            for (int it = 0; it < 4; it++)
                cpa16(&sA[ar + it * 32][ac], Ab + (ar + it * 32) * DDIM + ac);
        }
        const __nv_bfloat16* Bb = g_Bq + (size_t)b * DDIM * TDIM + n0;
        __nv_bfloat16 (*sB)[SB_COLS] = stageB(i % 3);
        #pragma unroll
        for (int it = 0; it < 4; it++)
            cpa16(&sB[br + it * 16][bc], Bb + (size_t)(br + it * 16) * TDIM + bc);
        asm volatile("cp.async.commit_group;");
    };

    const float s = g_scale;

    load_group(0);
    if (L > 1) load_group(1);

    for (int i = 0; i < L; i++) {
        if (i + 1 < L) {
            asm volatile("cp.async.wait_group 1;");   // this tile's group done
        } else {
            asm volatile("cp.async.wait_group 0;");
        }
        __syncthreads();   // single barrier per iteration

        const int k = i >> 3, j = i & 7;
        const int u = bid + k * GEMM_GRID;
        const int b  = u >> 5;
        const int m0 = ((u >> 1) & 15) * 128;
        const int n0 = (u & 1) * 1024 + j * 128;

        __nv_bfloat16 (*sA)[SA_COLS] = bufA(k & 1);
        __nv_bfloat16 (*sB)[SB_COLS] = stageB(i % 3);

        float acc[4][4][4];
        #pragma unroll
        for (int mi = 0; mi < 4; mi++)
            #pragma unroll
            for (int ni = 0; ni < 4; ni++)
                #pragma unroll
                for (int q = 0; q < 4; q++) acc[mi][ni][q] = 0.0f;

        #pragma unroll
        for (int ks = 0; ks < 4; ks++) {
            const int k0 = ks * 16;
            uint32_t af[4][4];
            #pragma unroll
            for (int mi = 0; mi < 4; mi++) {
                int r = wm * 64 + mi * 16 + (lane & 15);
                int c = k0 + (lane >> 4) * 8;
                uint32_t addr = (uint32_t)__cvta_generic_to_shared(&sA[r][c]);
                asm volatile(
                    "ldmatrix.sync.aligned.m8n8.x4.shared.b16 {%0,%1,%2,%3}, [%4];"
                    : "=r"(af[mi][0]), "=r"(af[mi][1]), "=r"(af[mi][2]), "=r"(af[mi][3])
                    : "r"(addr));
            }
            uint32_t bf[4][2];
            #pragma unroll
            for (int nj = 0; nj < 2; nj++) {
                int r = k0 + (lane & 7) + ((lane >> 3) & 1) * 8;
                int c = wn * 32 + nj * 16 + (lane >> 4) * 8;
                uint32_t addr = (uint32_t)__cvta_generic_to_shared(&sB[r][c]);
                uint32_t t0, t1, t2, t3;
                asm volatile(
                    "ldmatrix.sync.aligned.m8n8.x4.trans.shared.b16 {%0,%1,%2,%3}, [%4];"
                    : "=r"(t0), "=r"(t1), "=r"(t2), "=r"(t3)
                    : "r"(addr));
                bf[nj * 2 + 0][0] = t0; bf[nj * 2 + 0][1] = t1;
                bf[nj * 2 + 1][0] = t2; bf[nj * 2 + 1][1] = t3;
            }
            #pragma unroll
            for (int mi = 0; mi < 4; mi++)
                #pragma unroll
                for (int ni = 0; ni < 4; ni++) {
                    asm volatile(
                        "mma.sync.aligned.m16n8k16.row.col.f32.bf16.bf16.f32 "
                        "{%0,%1,%2,%3}, {%4,%5,%6,%7}, {%8,%9}, {%0,%1,%2,%3};"
                        : "+f"(acc[mi][ni][0]), "+f"(acc[mi][ni][1]),
                          "+f"(acc[mi][ni][2]), "+f"(acc[mi][ni][3])
                        : "r"(af[mi][0]), "r"(af[mi][1]), "r"(af[mi][2]), "r"(af[mi][3]),
                          "r"(bf[ni][0]), "r"(bf[ni][1]));
                }
        }

        // epilogue stores (evict-first; drain while loads for i+2 stream)
        {
            float* ob = out + (size_t)b * SDIM * TDIM;
            #pragma unroll
            for (int mi = 0; mi < 4; mi++) {
                #pragma unroll
                for (int ni = 0; ni < 4; ni++) {
                    int r = m0 + wm * 64 + mi * 16 + (lane >> 2);
                    int c = n0 + wn * 32 + ni * 8 + (lane & 3) * 2;
                    float2 v0 = make_float2(acc[mi][ni][0] * s, acc[mi][ni][1] * s);
                    float2 v1 = make_float2(acc[mi][ni][2] * s, acc[mi][ni][3] * s);
                    __stcs((float2*)&ob[(size_t)r * TDIM + c], v0);
                    __stcs((float2*)&ob[(size_t)(r + 8) * TDIM + c], v1);
                }
            }
        }

        // prefetch local tile i+2 (B stage (i+2)%3 != current/next; A goes to
        // the idle parity buffer — races excluded by the top barrier)
        if (i + 2 < L) load_group(i + 2);
    }
}

extern "C" void kernel_launch(void* const* d_in, const int* in_sizes, int n_in,
                              void* d_out, int out_size) {
    const float* A = (const float*)d_in[0];
    const float* B = (const float*)d_in[1];
    float* out = (float*)d_out;

    cudaFuncSetAttribute(k_gemm, cudaFuncAttributeMaxDynamicSharedMemorySize, SMEM_DYN);

    k_minmax<<<dim3(MM_BLOCKS, 1, 2), 256>>>(A, B);
    k_quant<<<dim3(2048, 1, 2), 256>>>(A, B);
    k_gemm<<<GEMM_GRID, 256, SMEM_DYN>>>(out);
}